// round 4
// baseline (speedup 1.0000x reference)
#include <cuda_runtime.h>
#include <cuda_bf16.h>
#include <math.h>

// Problem constants
#define BATCH 2
#define DGRID 128
#define DOUT  123
#define KC    6
#define CIN   3
#define COUT  3

// Tiling: one large CTA; thread dims (a=y, b=x-chunk, c=z)
#define TY 12
#define BX 4
#define TZ 6
#define RX 8
#define TX (BX*RX)             // 32
#define NTHREADS (TY*BX*TZ)    // 288 = 9 warps

// smem input tile (float2 {b0,b1}), layout [z][y][x*3+ci], row stride 114 f2 (912B)
#define SZ (TZ+5)              // 11
#define SY (TY+5)              // 17
#define SXU 111                // used f2 per row = (TX+5)*3
#define SROW 114               // padded: 912B == 16 mod 128 -> conflict-free phases
#define SPLANE (SY*SROW)       // 1938
#define SMEM_IN (SZ*SPLANE)    // 21318 f2
#define NW (KC*KC*KC*CIN*COUT) // 1944
#define SMEM_F2 (SMEM_IN + NW) // 23262 f2 = 186,096 B

typedef unsigned long long ull;

// ---------------- device scratch ----------------
__device__ float2 g_dense2[(size_t)DGRID*DGRID*DGRID*3];   // 50.3 MB, batch-paired
__device__ float  g_w12[4*4*4*3*5];
__device__ float2 g_wc2[NW];    // composed weights as {w,w} pairs, [kz][ky][kx][ci][co]

// ---------------- f32x2 helpers ----------------
__device__ __forceinline__ ull ffma2(ull a, ull b, ull c) {
    ull d;
    asm("fma.rn.f32x2 %0, %1, %2, %3;" : "=l"(d) : "l"(a), "l"(b), "l"(c));
    return d;
}
__device__ __forceinline__ void unpackf2(ull v, float& lo, float& hi) {
    asm("mov.b64 {%0, %1}, %2;" : "=f"(lo), "=f"(hi) : "l"(v));
}

// ---------------- weight composition ----------------
__global__ void compose_w12_kernel(const float* __restrict__ W1,
                                   const float* __restrict__ W2) {
    int idx = blockIdx.x * blockDim.x + threadIdx.x;
    if (idx >= 4*4*4*3*5) return;
    int c5 = idx % 5; int t = idx / 5;
    int ci = t % 3;   t /= 3;
    int kx = t % 4;   t /= 4;
    int ky = t % 4;   int kz = t / 4;
    float s = 0.f;
    for (int az = 0; az < 2; az++) {
        int bz = kz - az; if (bz < 0 || bz > 2) continue;
        for (int ay = 0; ay < 2; ay++) {
            int by = ky - ay; if (by < 0 || by > 2) continue;
            for (int ax = 0; ax < 2; ax++) {
                int bx = kx - ax; if (bx < 0 || bx > 2) continue;
                const float* w1 = W1 + (((az*2 + ay)*2 + ax)*3 + ci)*9;
                const float* w2 = W2 + ((bz*3 + by)*3 + bx)*9*5;
                #pragma unroll
                for (int m = 0; m < 9; m++)
                    s += w1[m] * w2[m*5 + c5];
            }
        }
    }
    g_w12[idx] = s;
}

__global__ void compose_wc_kernel(const float* __restrict__ W3) {
    int idx = blockIdx.x * blockDim.x + threadIdx.x;
    if (idx >= NW) return;
    int co = idx % 3; int t = idx / 3;
    int ci = t % 3;   t /= 3;
    int kx = t % 6;   t /= 6;
    int ky = t % 6;   int kz = t / 6;
    float s = 0.f;
    for (int dz = 0; dz < 4; dz++) {
        int ez = kz - dz; if (ez < 0 || ez > 2) continue;
        for (int dy = 0; dy < 4; dy++) {
            int ey = ky - dy; if (ey < 0 || ey > 2) continue;
            for (int dx = 0; dx < 4; dx++) {
                int ex = kx - dx; if (ex < 0 || ex > 2) continue;
                const float* w12 = g_w12 + (((dz*4 + dy)*4 + dx)*3 + ci)*5;
                const float* w3  = W3 + ((ez*3 + ey)*3 + ex)*5*3;
                #pragma unroll
                for (int c5 = 0; c5 < 5; c5++)
                    s += w12[c5] * w3[c5*3 + co];
            }
        }
    }
    g_wc2[idx] = make_float2(s, s);
}

// ---------------- scatter (into batch-paired grid) ----------------
__global__ void scatter_kernel(const int* __restrict__ coords,
                               const float* __restrict__ voxels, int n) {
    int i = blockIdx.x * blockDim.x + threadIdx.x;
    if (i >= n) return;
    int b = coords[4*i + 0];
    int z = coords[4*i + 1];
    int y = coords[4*i + 2];
    int x = coords[4*i + 3];
    size_t base = (((size_t)z*DGRID + y)*DGRID + x) * 3;   // f2 index
    float* g = (float*)g_dense2;
    atomicAdd(&g[(base + 0)*2 + b], voxels[3*i + 0]);
    atomicAdd(&g[(base + 1)*2 + b], voxels[3*i + 1]);
    atomicAdd(&g[(base + 2)*2 + b], voxels[3*i + 2]);
}

// ---------------- fused 6x6x6 conv, batch-paired FFMA2 ----------------
__global__ __launch_bounds__(NTHREADS, 1)
void conv6_kernel(const float* __restrict__ b3, float* __restrict__ out) {
    extern __shared__ float2 smem[];   // SMEM_F2 pairs
    float2* wsm = smem + SMEM_IN;

    const int a = threadIdx.x;         // 0..11 : y within tile (FAST lane dim)
    const int b = threadIdx.y;         // 0..3  : x chunk
    const int c = threadIdx.z;         // 0..5  : z within tile
    const int tid = a + TY*(b + BX*c);

    const int x0 = blockIdx.x * TX;
    const int y0 = blockIdx.y * TY;
    const int z0 = blockIdx.z * TZ;

    // ---- cooperative load: 11 x 17 x 111 f2 tile, zero-padded at grid edges ----
    {
        const int xf0 = x0 * 3;
        for (int i = tid; i < SZ*SY*SXU; i += NTHREADS) {
            int zz = i / (SY*SXU);
            int r  = i - zz*(SY*SXU);
            int yy = r / SXU;
            int xc = r - yy*SXU;
            int gz = z0 + zz;
            int gy = y0 + yy;
            int gxc = xf0 + xc;
            float2 v = make_float2(0.f, 0.f);
            if (gz < DGRID && gy < DGRID && gxc < DGRID*3)
                v = g_dense2[((size_t)gz*DGRID + gy)*(DGRID*3) + gxc];
            smem[(zz*SY + yy)*SROW + xc] = v;
        }
        for (int i = tid; i < NW; i += NTHREADS)
            wsm[i] = g_wc2[i];
    }
    __syncthreads();

    ull acc[RX][COUT];
    #pragma unroll
    for (int j = 0; j < RX; j++)
        #pragma unroll
        for (int cc = 0; cc < COUT; cc++) acc[j][cc] = 0ull;

    #pragma unroll 1
    for (int kz = 0; kz < KC; kz++) {
        #pragma unroll 1
        for (int ky = 0; ky < KC; ky++) {
            // contiguous row segment: 40 f2 as 20 float4 loads (conflict-free)
            const float4* rp = (const float4*)&smem[((c + kz)*SY + (a + ky))*SROW + b*(RX*3)];
            union { float4 q[20]; ull p[40]; } r;
            #pragma unroll
            for (int i = 0; i < 20; i++) r.q[i] = rp[i];

            const float2* wrow = wsm + (kz*KC + ky)*KC*CIN*COUT;

            #pragma unroll
            for (int kx = 0; kx < KC; kx++) {
                #pragma unroll
                for (int ci = 0; ci < CIN; ci++) {
                    const ull* wp = (const ull*)(wrow + (kx*CIN + ci)*COUT);
                    ull w0 = wp[0], w1 = wp[1], w2 = wp[2];   // LDS.64 broadcast
                    #pragma unroll
                    for (int j = 0; j < RX; j++) {
                        ull xv = r.p[3*(j + kx) + ci];
                        acc[j][0] = ffma2(xv, w0, acc[j][0]);
                        acc[j][1] = ffma2(xv, w1, acc[j][1]);
                        acc[j][2] = ffma2(xv, w2, acc[j][2]);
                    }
                }
            }
        }
    }

    // ---- epilogue: bias + relu + store both batches ----
    const float bb0 = b3[0], bb1 = b3[1], bb2 = b3[2];
    const float bbv[3] = { bb0, bb1, bb2 };
    const int oz = z0 + c;
    const int oy = y0 + a;
    if (oz < DOUT && oy < DOUT) {
        const int oxb = x0 + b*RX;
        const size_t bstride = (size_t)DOUT*DOUT*DOUT*3;
        size_t rowbase = ((size_t)oz*DOUT + oy) * (size_t)DOUT * 3;
        #pragma unroll
        for (int j = 0; j < RX; j++) {
            int ox = oxb + j;
            if (ox < DOUT) {
                size_t o = rowbase + (size_t)ox*3;
                #pragma unroll
                for (int cc = 0; cc < COUT; cc++) {
                    float v0, v1;
                    unpackf2(acc[j][cc], v0, v1);
                    out[o + cc]           = fmaxf(v0 + bbv[cc], 0.f);
                    out[bstride + o + cc] = fmaxf(v1 + bbv[cc], 0.f);
                }
            }
        }
    }
}

// ---------------- launch ----------------
extern "C" void kernel_launch(void* const* d_in, const int* in_sizes, int n_in,
                              void* d_out, int out_size) {
    const int*   coords = (const int*)  d_in[0];
    const float* voxels = (const float*)d_in[1];
    const float* W1     = (const float*)d_in[2];
    const float* W2     = (const float*)d_in[3];
    const float* W3     = (const float*)d_in[4];
    const float* b3     = (const float*)d_in[5];
    float*       out    = (float*)d_out;

    const int n = in_sizes[0] / 4;

    compose_w12_kernel<<< (4*4*4*3*5 + 255)/256, 256 >>>(W1, W2);
    compose_wc_kernel<<< (NW + 255)/256, 256 >>>(W3);

    void* densep = nullptr;
    cudaGetSymbolAddress(&densep, g_dense2);
    cudaMemsetAsync(densep, 0, (size_t)DGRID*DGRID*DGRID*3*sizeof(float2));

    scatter_kernel<<< (n + 255)/256, 256 >>>(coords, voxels, n);

    const size_t smem_bytes = (size_t)SMEM_F2 * sizeof(float2);   // 186,096 B
    cudaFuncSetAttribute(conv6_kernel,
                         cudaFuncAttributeMaxDynamicSharedMemorySize,
                         (int)smem_bytes);
    dim3 block(TY, BX, TZ);                 // (12,4,6) = 288 threads
    dim3 grid((DOUT + TX - 1)/TX,           // 4
              (DOUT + TY - 1)/TY,           // 11
              (DOUT + TZ - 1)/TZ);          // 21
    conv6_kernel<<<grid, block, smem_bytes>>>(b3, out);
}

// round 7
// speedup vs baseline: 1.2117x; 1.2117x over previous
#include <cuda_runtime.h>
#include <cuda_bf16.h>
#include <math.h>

// Problem constants
#define BATCH 2
#define DGRID 128
#define DMID  125          // after 4^3 composed conv
#define DOUT  123          // after 3^3 conv
#define CIN   3
#define CMID  5
#define COUT  3

// ---------------- device scratch ----------------
__device__ float g_dense[(size_t)BATCH*DGRID*DGRID*DGRID*3];          // 50.3 MB [b][z][y][x*3+c]
__device__ float g_mid  [(size_t)BATCH*DMID*DMID*DMID*CMID];          // 78.1 MB [b][z][y][x*5+c]
__device__ float g_w12  [4*4*4*3*5];   // [kz][ky][kx][ci][c5] == [kz][ky][t=kx*3+ci][c5]

// ---------------- weight composition: W12 = W1 (*) W2  (4^3, 3->5) ----------------
__global__ void compose_w12_kernel(const float* __restrict__ W1,
                                   const float* __restrict__ W2) {
    int idx = blockIdx.x * blockDim.x + threadIdx.x;
    if (idx >= 4*4*4*3*5) return;
    int c5 = idx % 5; int t = idx / 5;
    int ci = t % 3;   t /= 3;
    int kx = t % 4;   t /= 4;
    int ky = t % 4;   int kz = t / 4;
    float s = 0.f;
    for (int az = 0; az < 2; az++) {
        int bz = kz - az; if (bz < 0 || bz > 2) continue;
        for (int ay = 0; ay < 2; ay++) {
            int by = ky - ay; if (by < 0 || by > 2) continue;
            for (int ax = 0; ax < 2; ax++) {
                int bx = kx - ax; if (bx < 0 || bx > 2) continue;
                const float* w1 = W1 + (((az*2 + ay)*2 + ax)*3 + ci)*9;
                const float* w2 = W2 + ((bz*3 + by)*3 + bx)*9*5;
                #pragma unroll
                for (int m = 0; m < 9; m++)
                    s += w1[m] * w2[m*5 + c5];
            }
        }
    }
    g_w12[idx] = s;
}

// ---------------- scatter ----------------
__global__ void scatter_kernel(const int* __restrict__ coords,
                               const float* __restrict__ voxels, int n) {
    int i = blockIdx.x * blockDim.x + threadIdx.x;
    if (i >= n) return;
    int b = coords[4*i + 0];
    int z = coords[4*i + 1];
    int y = coords[4*i + 2];
    int x = coords[4*i + 3];
    size_t base = ((((size_t)b*DGRID + z)*DGRID + y)*DGRID + x) * 3;
    atomicAdd(&g_dense[base + 0], voxels[3*i + 0]);
    atomicAdd(&g_dense[base + 1], voxels[3*i + 1]);
    atomicAdd(&g_dense[base + 2], voxels[3*i + 2]);
}

// ================= Stage A: 4^3 conv, 3ch -> 5ch =================
// block (4,8,4)=128, outputs/thread: 8 along x
#define ABX 4
#define ATY 8
#define ATZ 4
#define ARX 8
#define ATX (ABX*ARX)        // 32
#define ASZ (ATZ+3)          // 7
#define ASY (ATY+3)          // 11
#define ASROW 108            // (ATX+3)*3 = 105 used, pad to 108 (432B: conflict-free)
#define ANW (4*4*4*3*5)      // 960
#define A_SMEM (ASZ*ASY*ASROW + ANW)

__global__ __launch_bounds__(128, 4)
void convA_kernel(float* __restrict__ dummy) {
    __shared__ float smem[A_SMEM];
    float* wsm = smem + ASZ*ASY*ASROW;

    const int tx = threadIdx.x, ty = threadIdx.y, tz = threadIdx.z;
    const int tid = tx + ABX*(ty + ATY*tz);

    const int x0 = blockIdx.x * ATX;
    const int y0 = blockIdx.y * ATY;
    const int NBZ = (DMID + ATZ - 1) / ATZ;   // 32
    const int b  = blockIdx.z / NBZ;
    const int z0 = (blockIdx.z % NBZ) * ATZ;

    // cooperative tile load (zero-padded at edges)
    {
        const int xf0 = x0 * 3;
        const float* src = g_dense + (size_t)b*DGRID*DGRID*DGRID*3;
        for (int i = tid; i < ASZ*ASY*ASROW; i += 128) {
            int zz = i / (ASY*ASROW);
            int r  = i - zz*(ASY*ASROW);
            int yy = r / ASROW;
            int xc = r - yy*ASROW;
            int gz = z0 + zz, gy = y0 + yy, gxc = xf0 + xc;
            float v = 0.f;
            if (gz < DGRID && gy < DGRID && gxc < DGRID*3)
                v = src[((size_t)gz*DGRID + gy)*(DGRID*3) + gxc];
            smem[i] = v;
        }
        for (int i = tid; i < ANW; i += 128) wsm[i] = g_w12[i];
    }
    __syncthreads();

    float acc[ARX][CMID];
    #pragma unroll
    for (int j = 0; j < ARX; j++)
        #pragma unroll
        for (int c = 0; c < CMID; c++) acc[j][c] = 0.f;

    #pragma unroll 1
    for (int kz = 0; kz < 4; kz++) {
        #pragma unroll 1
        for (int ky = 0; ky < 4; ky++) {
            const float4* rp = (const float4*)&smem[((tz + kz)*ASY + (ty + ky))*ASROW + tx*(ARX*3)];
            union { float4 q[9]; float f[36]; } r;
            #pragma unroll
            for (int i = 0; i < 9; i++) r.q[i] = rp[i];

            const float* wp = wsm + (kz*4 + ky)*60;   // 12 taps x 5 cout
            #pragma unroll
            for (int t = 0; t < 12; t++) {
                float w0 = wp[t*5+0], w1 = wp[t*5+1], w2 = wp[t*5+2],
                      w3 = wp[t*5+3], w4 = wp[t*5+4];
                #pragma unroll
                for (int j = 0; j < ARX; j++) {
                    float xv = r.f[j*3 + t];
                    acc[j][0] = fmaf(xv, w0, acc[j][0]);
                    acc[j][1] = fmaf(xv, w1, acc[j][1]);
                    acc[j][2] = fmaf(xv, w2, acc[j][2]);
                    acc[j][3] = fmaf(xv, w3, acc[j][3]);
                    acc[j][4] = fmaf(xv, w4, acc[j][4]);
                }
            }
        }
    }

    // store
    const int oz = z0 + tz, oy = y0 + ty;
    if (oz < DMID && oy < DMID) {
        float* dst = g_mid + ((size_t)b*DMID + oz)*(size_t)DMID*DMID*CMID
                   + (size_t)oy*DMID*CMID;
        const int oxb = x0 + tx*ARX;
        #pragma unroll
        for (int j = 0; j < ARX; j++) {
            int ox = oxb + j;
            if (ox < DMID) {
                #pragma unroll
                for (int c = 0; c < CMID; c++)
                    dst[ox*CMID + c] = acc[j][c];
            }
        }
    }
}

// ================= Stage B: 3^3 conv, 5ch -> 3ch, +bias, relu =================
#define BBX 4
#define BTY 8
#define BTZ 4
#define BRX 8
#define BTX (BBX*BRX)        // 32
#define BSZ (BTZ+2)          // 6
#define BSY (BTY+2)          // 10
#define BSROW 172            // (BTX+2)*5 = 170 used, pad to 172 (688B: conflict-free)
#define BNW (27*5*3)         // 405
#define B_SMEM (BSZ*BSY*BSROW + BNW)

__global__ __launch_bounds__(128, 4)
void convB_kernel(const float* __restrict__ W3, const float* __restrict__ b3,
                  float* __restrict__ out) {
    __shared__ float smem[B_SMEM];
    float* wsm = smem + BSZ*BSY*BSROW;

    const int tx = threadIdx.x, ty = threadIdx.y, tz = threadIdx.z;
    const int tid = tx + BBX*(ty + BTY*tz);

    const int x0 = blockIdx.x * BTX;
    const int y0 = blockIdx.y * BTY;
    const int NBZ = (DOUT + BTZ - 1) / BTZ;   // 31
    const int b  = blockIdx.z / NBZ;
    const int z0 = (blockIdx.z % NBZ) * BTZ;

    {
        const int xf0 = x0 * CMID;
        const float* src = g_mid + (size_t)b*DMID*DMID*DMID*CMID;
        for (int i = tid; i < BSZ*BSY*BSROW; i += 128) {
            int zz = i / (BSY*BSROW);
            int r  = i - zz*(BSY*BSROW);
            int yy = r / BSROW;
            int xc = r - yy*BSROW;
            int gz = z0 + zz, gy = y0 + yy, gxc = xf0 + xc;
            float v = 0.f;
            if (gz < DMID && gy < DMID && gxc < DMID*CMID)
                v = src[((size_t)gz*DMID + gy)*(DMID*CMID) + gxc];
            smem[i] = v;
        }
        // W3 layout [kz][ky][kx][ci][co] == [row][t=kx*5+ci][co] : use directly
        for (int i = tid; i < BNW; i += 128) wsm[i] = W3[i];
    }
    __syncthreads();

    float acc[BRX][COUT];
    #pragma unroll
    for (int j = 0; j < BRX; j++)
        #pragma unroll
        for (int c = 0; c < COUT; c++) acc[j][c] = 0.f;

    #pragma unroll 1
    for (int kz = 0; kz < 3; kz++) {
        #pragma unroll 1
        for (int ky = 0; ky < 3; ky++) {
            const float4* rp = (const float4*)&smem[((tz + kz)*BSY + (ty + ky))*BSROW + tx*(BRX*CMID)];
            union { float4 q[13]; float f[52]; } r;
            #pragma unroll
            for (int i = 0; i < 13; i++) r.q[i] = rp[i];

            const float* wp = wsm + (kz*3 + ky)*45;   // 15 taps x 3 cout
            #pragma unroll
            for (int t = 0; t < 15; t++) {
                float w0 = wp[t*3+0], w1 = wp[t*3+1], w2 = wp[t*3+2];
                #pragma unroll
                for (int j = 0; j < BRX; j++) {
                    float xv = r.f[j*CMID + t];
                    acc[j][0] = fmaf(xv, w0, acc[j][0]);
                    acc[j][1] = fmaf(xv, w1, acc[j][1]);
                    acc[j][2] = fmaf(xv, w2, acc[j][2]);
                }
            }
        }
    }

    const float bb0 = b3[0], bb1 = b3[1], bb2 = b3[2];
    const int oz = z0 + tz, oy = y0 + ty;
    if (oz < DOUT && oy < DOUT) {
        float* dst = out + ((size_t)b*DOUT + oz)*(size_t)DOUT*DOUT*COUT
                   + (size_t)oy*DOUT*COUT;
        const int oxb = x0 + tx*BRX;
        #pragma unroll
        for (int j = 0; j < BRX; j++) {
            int ox = oxb + j;
            if (ox < DOUT) {
                dst[ox*COUT + 0] = fmaxf(acc[j][0] + bb0, 0.f);
                dst[ox*COUT + 1] = fmaxf(acc[j][1] + bb1, 0.f);
                dst[ox*COUT + 2] = fmaxf(acc[j][2] + bb2, 0.f);
            }
        }
    }
}

// ---------------- launch ----------------
extern "C" void kernel_launch(void* const* d_in, const int* in_sizes, int n_in,
                              void* d_out, int out_size) {
    const int*   coords = (const int*)  d_in[0];
    const float* voxels = (const float*)d_in[1];
    const float* W1     = (const float*)d_in[2];
    const float* W2     = (const float*)d_in[3];
    const float* W3     = (const float*)d_in[4];
    const float* b3     = (const float*)d_in[5];
    float*       out    = (float*)d_out;

    const int n = in_sizes[0] / 4;

    compose_w12_kernel<<< (4*4*4*3*5 + 255)/256, 256 >>>(W1, W2);

    void* densep = nullptr;
    cudaGetSymbolAddress(&densep, g_dense);
    cudaMemsetAsync(densep, 0, (size_t)BATCH*DGRID*DGRID*DGRID*3*sizeof(float));

    scatter_kernel<<< (n + 255)/256, 256 >>>(coords, voxels, n);

    {   // Stage A: 4^3 conv 3->5
        dim3 block(ABX, ATY, ATZ);
        dim3 grid((DMID + ATX - 1)/ATX,           // 4
                  (DMID + ATY - 1)/ATY,           // 16
                  BATCH * ((DMID + ATZ - 1)/ATZ)); // 64
        convA_kernel<<<grid, block>>>(nullptr);
    }
    {   // Stage B: 3^3 conv 5->3 + bias + relu
        dim3 block(BBX, BTY, BTZ);
        dim3 grid((DOUT + BTX - 1)/BTX,           // 4
                  (DOUT + BTY - 1)/BTY,           // 16
                  BATCH * ((DOUT + BTZ - 1)/BTZ)); // 62
        convB_kernel<<<grid, block>>>(W3, b3, out);
    }
}

// round 9
// speedup vs baseline: 1.5943x; 1.3158x over previous
#include <cuda_runtime.h>
#include <cuda_bf16.h>
#include <math.h>

// Problem constants
#define BATCH 2
#define DGRID 128
#define DMID  125          // after 4^3 composed conv
#define DOUT  123          // after 3^3 conv
#define CIN   3
#define CMID  5
#define COUT  3
#define MROW  628          // padded g_mid row stride (floats), 16B-aligned (625 used)

// ---------------- device scratch ----------------
__device__ float g_dense[(size_t)BATCH*DGRID*DGRID*DGRID*3 + 128];    // [b][z][y][x*3+c] (+pad)
__device__ float g_mid  [(size_t)BATCH*DMID*DMID*MROW + 128];         // [b][z][y][x*5+c] (+pad)
__device__ float g_w12  [4*4*4*3*5];   // [kz][ky][t=kx*3+ci][c5]

// ---------------- weight composition: W12 = W1 (*) W2  (4^3, 3->5) ----------------
__global__ void compose_w12_kernel(const float* __restrict__ W1,
                                   const float* __restrict__ W2) {
    int idx = blockIdx.x * blockDim.x + threadIdx.x;
    if (idx >= 4*4*4*3*5) return;
    int c5 = idx % 5; int t = idx / 5;
    int ci = t % 3;   t /= 3;
    int kx = t % 4;   t /= 4;
    int ky = t % 4;   int kz = t / 4;
    float s = 0.f;
    for (int az = 0; az < 2; az++) {
        int bz = kz - az; if (bz < 0 || bz > 2) continue;
        for (int ay = 0; ay < 2; ay++) {
            int by = ky - ay; if (by < 0 || by > 2) continue;
            for (int ax = 0; ax < 2; ax++) {
                int bx = kx - ax; if (bx < 0 || bx > 2) continue;
                const float* w1 = W1 + (((az*2 + ay)*2 + ax)*3 + ci)*9;
                const float* w2 = W2 + ((bz*3 + by)*3 + bx)*9*5;
                #pragma unroll
                for (int m = 0; m < 9; m++)
                    s += w1[m] * w2[m*5 + c5];
            }
        }
    }
    g_w12[idx] = s;
}

// ---------------- scatter ----------------
__global__ void scatter_kernel(const int* __restrict__ coords,
                               const float* __restrict__ voxels, int n) {
    int i = blockIdx.x * blockDim.x + threadIdx.x;
    if (i >= n) return;
    int b = coords[4*i + 0];
    int z = coords[4*i + 1];
    int y = coords[4*i + 2];
    int x = coords[4*i + 3];
    size_t base = ((((size_t)b*DGRID + z)*DGRID + y)*DGRID + x) * 3;
    atomicAdd(&g_dense[base + 0], voxels[3*i + 0]);
    atomicAdd(&g_dense[base + 1], voxels[3*i + 1]);
    atomicAdd(&g_dense[base + 2], voxels[3*i + 2]);
}

// ================= Stage A: 4^3 conv, 3ch -> 5ch =================
#define ABX 4
#define ATY 8
#define ATZ 4
#define ARX 8
#define ATX (ABX*ARX)        // 32
#define ASZ (ATZ+3)          // 7
#define ASY (ATY+3)          // 11
#define ASROW 108            // 27 float4; 105 used
#define ANW (4*4*4*3*5)      // 960
#define A_SMEM (ASZ*ASY*ASROW + ANW)

__global__ __launch_bounds__(128, 5)
void convA_kernel() {
    __shared__ float smem[A_SMEM];
    float* wsm = smem + ASZ*ASY*ASROW;

    const int tx = threadIdx.x, ty = threadIdx.y, tz = threadIdx.z;
    const int tid = tx + ABX*(ty + ATY*tz);

    const int x0 = blockIdx.x * ATX;
    const int y0 = blockIdx.y * ATY;
    const int NBZ = (DMID + ATZ - 1) / ATZ;   // 32
    const int b  = blockIdx.z / NBZ;
    const int z0 = (blockIdx.z % NBZ) * ATZ;

    // ---- tile load: float4, clamp-indexed ----
    {
        const float4* src4 = (const float4*)(g_dense + (size_t)b*DGRID*DGRID*DGRID*3);
        const int xq0 = (x0*3) >> 2;
        float4* s4 = (float4*)smem;
        #pragma unroll 1
        for (int i = tid; i < ASZ*ASY*27; i += 128) {
            int zz = i / (ASY*27);
            int r  = i - zz*(ASY*27);
            int yy = r / 27;
            int xq = r - yy*27;
            int gz = min(z0 + zz, DGRID-1);
            int gy = min(y0 + yy, DGRID-1);
            s4[(zz*ASY + yy)*27 + xq] = src4[(size_t)(gz*DGRID + gy)*96 + xq0 + xq];
        }
        for (int i = tid; i < ANW; i += 128) wsm[i] = g_w12[i];
    }
    __syncthreads();

    float acc[ARX][CMID];
    #pragma unroll
    for (int j = 0; j < ARX; j++)
        #pragma unroll
        for (int c = 0; c < CMID; c++) acc[j][c] = 0.f;

    #pragma unroll 1
    for (int kz = 0; kz < 4; kz++) {
        #pragma unroll 1
        for (int ky = 0; ky < 4; ky++) {
            const float4* rp = (const float4*)&smem[((tz + kz)*ASY + (ty + ky))*ASROW + tx*(ARX*3)];
            union { float4 q[9]; float f[36]; } r;
            #pragma unroll
            for (int i = 0; i < 9; i++) r.q[i] = rp[i];

            const float* wp = wsm + (kz*4 + ky)*60;   // 12 taps x 5 cout
            #pragma unroll
            for (int t = 0; t < 12; t++) {
                float w0 = wp[t*5+0], w1 = wp[t*5+1], w2 = wp[t*5+2],
                      w3 = wp[t*5+3], w4 = wp[t*5+4];
                #pragma unroll
                for (int j = 0; j < ARX; j++) {
                    float xv = r.f[j*3 + t];
                    acc[j][0] = fmaf(xv, w0, acc[j][0]);
                    acc[j][1] = fmaf(xv, w1, acc[j][1]);
                    acc[j][2] = fmaf(xv, w2, acc[j][2]);
                    acc[j][3] = fmaf(xv, w3, acc[j][3]);
                    acc[j][4] = fmaf(xv, w4, acc[j][4]);
                }
            }
        }
    }

    // ---- store (f4 fast path on interior x tiles; g_mid rows are 16B-aligned) ----
    const int oz = z0 + tz, oy = y0 + ty;
    if (oz < DMID && oy < DMID) {
        float* dst = g_mid + (((size_t)b*DMID + oz)*DMID + oy)*(size_t)MROW;
        const int oxb = x0 + tx*ARX;
        if (x0 + ATX <= DMID) {
            union { float f[40]; float4 q[10]; } o;
            #pragma unroll
            for (int j = 0; j < ARX; j++)
                #pragma unroll
                for (int c = 0; c < CMID; c++) o.f[j*5 + c] = acc[j][c];
            float4* d4 = (float4*)(dst + oxb*CMID);
            #pragma unroll
            for (int q = 0; q < 10; q++) d4[q] = o.q[q];
        } else {
            #pragma unroll
            for (int j = 0; j < ARX; j++) {
                int ox = oxb + j;
                if (ox < DMID) {
                    #pragma unroll
                    for (int c = 0; c < CMID; c++)
                        dst[ox*CMID + c] = acc[j][c];
                }
            }
        }
    }
}

// ================= Stage B: 3^3 conv, 5ch -> 3ch, +bias, relu =================
#define BBX 4
#define BTY 8
#define BTZ 4
#define BRX 8
#define BTX (BBX*BRX)        // 32
#define BSZ (BTZ+2)          // 6
#define BSY (BTY+2)          // 10
#define BSROW 172            // 43 float4; 170 used
#define BW_ROW 48            // padded weight row stride (45 used)

__global__ __launch_bounds__(128, 5)
void convB_kernel(const float* __restrict__ W3, const float* __restrict__ b3,
                  float* __restrict__ out) {
    __shared__ float smem[BSZ*BSY*BSROW + 9*BW_ROW];   // 10320 + 432 floats
    float* wsm = smem + BSZ*BSY*BSROW;

    const int tx = threadIdx.x, ty = threadIdx.y, tz = threadIdx.z;
    const int tid = tx + BBX*(ty + BTY*tz);

    const int x0 = blockIdx.x * BTX;
    const int y0 = blockIdx.y * BTY;
    const int NBZ = (DOUT + BTZ - 1) / BTZ;   // 31
    const int b  = blockIdx.z / NBZ;
    const int z0 = (blockIdx.z % NBZ) * BTZ;

    // ---- tile load: float4 with clamps (g_mid rows padded & aligned) ----
    {
        const float4* src4 = (const float4*)(g_mid + (size_t)b*DMID*DMID*MROW);
        const int xq0 = (x0*CMID) >> 2;
        float4* s4 = (float4*)smem;
        #pragma unroll 1
        for (int i = tid; i < BSZ*BSY*43; i += 128) {
            int zz = i / (BSY*43);
            int r  = i - zz*(BSY*43);
            int yy = r / 43;
            int xq = r - yy*43;
            int gz = min(z0 + zz, DMID-1);
            int gy = min(y0 + yy, DMID-1);
            s4[(zz*BSY + yy)*43 + xq] = src4[(size_t)(gz*DMID + gy)*(MROW/4) + xq0 + xq];
        }
        for (int i = tid; i < 9*45; i += 128) {
            int row = i / 45, t = i - row*45;
            wsm[row*BW_ROW + t] = W3[row*45 + t];
        }
    }
    __syncthreads();

    float acc[BRX][COUT];
    #pragma unroll
    for (int j = 0; j < BRX; j++)
        #pragma unroll
        for (int c = 0; c < COUT; c++) acc[j][c] = 0.f;

    #pragma unroll 1
    for (int kz = 0; kz < 3; kz++) {
        #pragma unroll 1
        for (int ky = 0; ky < 3; ky++) {
            const float4* rp = (const float4*)&smem[((tz + kz)*BSY + (ty + ky))*BSROW + tx*(BRX*CMID)];
            union { float4 q[13]; float f[52]; } r;
            #pragma unroll
            for (int i = 0; i < 13; i++) r.q[i] = rp[i];

            const float* wp = wsm + (kz*3 + ky)*BW_ROW;   // 15 taps x 3 cout
            #pragma unroll
            for (int t = 0; t < 15; t++) {
                float w0 = wp[t*3+0], w1 = wp[t*3+1], w2 = wp[t*3+2];
                #pragma unroll
                for (int j = 0; j < BRX; j++) {
                    float xv = r.f[j*CMID + t];
                    acc[j][0] = fmaf(xv, w0, acc[j][0]);
                    acc[j][1] = fmaf(xv, w1, acc[j][1]);
                    acc[j][2] = fmaf(xv, w2, acc[j][2]);
                }
            }
        }
    }

    // ---- epilogue: scalar stores ONLY (out rows are 369 floats -> 4B aligned only) ----
    const float bb0 = b3[0], bb1 = b3[1], bb2 = b3[2];
    const int oz = z0 + tz, oy = y0 + ty;
    if (oz < DOUT && oy < DOUT) {
        float* dst = out + (((size_t)b*DOUT + oz)*DOUT + oy)*(size_t)(DOUT*COUT);
        const int oxb = x0 + tx*BRX;
        #pragma unroll
        for (int j = 0; j < BRX; j++) {
            int ox = oxb + j;
            if (ox < DOUT) {
                dst[ox*COUT + 0] = fmaxf(acc[j][0] + bb0, 0.f);
                dst[ox*COUT + 1] = fmaxf(acc[j][1] + bb1, 0.f);
                dst[ox*COUT + 2] = fmaxf(acc[j][2] + bb2, 0.f);
            }
        }
    }
}

// ---------------- launch ----------------
extern "C" void kernel_launch(void* const* d_in, const int* in_sizes, int n_in,
                              void* d_out, int out_size) {
    const int*   coords = (const int*)  d_in[0];
    const float* voxels = (const float*)d_in[1];
    const float* W1     = (const float*)d_in[2];
    const float* W2     = (const float*)d_in[3];
    const float* W3     = (const float*)d_in[4];
    const float* b3     = (const float*)d_in[5];
    float*       out    = (float*)d_out;

    const int n = in_sizes[0] / 4;

    compose_w12_kernel<<< (4*4*4*3*5 + 255)/256, 256 >>>(W1, W2);

    void* densep = nullptr;
    cudaGetSymbolAddress(&densep, g_dense);
    cudaMemsetAsync(densep, 0, (size_t)BATCH*DGRID*DGRID*DGRID*3*sizeof(float));

    scatter_kernel<<< (n + 255)/256, 256 >>>(coords, voxels, n);

    {   // Stage A: 4^3 conv 3->5
        dim3 block(ABX, ATY, ATZ);
        dim3 grid((DMID + ATX - 1)/ATX,            // 4
                  (DMID + ATY - 1)/ATY,            // 16
                  BATCH * ((DMID + ATZ - 1)/ATZ)); // 64
        convA_kernel<<<grid, block>>>();
    }
    {   // Stage B: 3^3 conv 5->3 + bias + relu
        dim3 block(BBX, BTY, BTZ);
        dim3 grid((DOUT + BTX - 1)/BTX,            // 4
                  (DOUT + BTY - 1)/BTY,            // 16
                  BATCH * ((DOUT + BTZ - 1)/BTZ)); // 62
        convB_kernel<<<grid, block>>>(W3, b3, out);
    }
}

// round 11
// speedup vs baseline: 1.6056x; 1.0071x over previous
#include <cuda_runtime.h>
#include <cuda_bf16.h>
#include <math.h>

// Problem constants
#define BATCH 2
#define DGRID 128
#define DMID  125          // after 4^3 composed conv
#define DOUT  123          // after 3^3 conv
#define CIN   3
#define CMID  5
#define COUT  3

// ---------------- device scratch ----------------
// mid grid: [b][z][y][x][8]  (two float4 slots per voxel: ch0-3, ch4+pad)
__device__ float4 g_mid4[(size_t)BATCH*DMID*DMID*DMID*2 + 8];
__device__ float  g_w12 [4*4*4*3*5];   // [tap=(kz*4+ky)*4+kx][ci][c5]

// ---------------- weight composition: W12 = W1 (*) W2  (4^3, 3->5) ----------------
__global__ void compose_w12_kernel(const float* __restrict__ W1,
                                   const float* __restrict__ W2) {
    int idx = blockIdx.x * blockDim.x + threadIdx.x;
    if (idx >= 4*4*4*3*5) return;
    int c5 = idx % 5; int t = idx / 5;
    int ci = t % 3;   t /= 3;
    int kx = t % 4;   t /= 4;
    int ky = t % 4;   int kz = t / 4;
    float s = 0.f;
    for (int az = 0; az < 2; az++) {
        int bz = kz - az; if (bz < 0 || bz > 2) continue;
        for (int ay = 0; ay < 2; ay++) {
            int by = ky - ay; if (by < 0 || by > 2) continue;
            for (int ax = 0; ax < 2; ax++) {
                int bx = kx - ax; if (bx < 0 || bx > 2) continue;
                const float* w1 = W1 + (((az*2 + ay)*2 + ax)*3 + ci)*9;
                const float* w2 = W2 + ((bz*3 + by)*3 + bx)*9*5;
                #pragma unroll
                for (int m = 0; m < 9; m++)
                    s += w1[m] * w2[m*5 + c5];
            }
        }
    }
    g_w12[idx] = s;
}

// ---------------- Stage A as sparse scatter: voxel x tap -> g_mid4 ----------------
// grid: (ceil(n/256), 64);  blockIdx.y = tap (uniform weights per block)
__global__ __launch_bounds__(256)
void scatterA_kernel(const int* __restrict__ coords,
                     const float* __restrict__ voxels, int n) {
    const int v   = blockIdx.x * blockDim.x + threadIdx.x;
    const int tap = blockIdx.y;

    // uniform per-block weights: W12[tap][ci][c5]
    const float* w = g_w12 + tap * 15;
    float w00=__ldg(w+0),  w01=__ldg(w+1),  w02=__ldg(w+2),  w03=__ldg(w+3),  w04=__ldg(w+4);
    float w10=__ldg(w+5),  w11=__ldg(w+6),  w12=__ldg(w+7),  w13=__ldg(w+8),  w14=__ldg(w+9);
    float w20=__ldg(w+10), w21=__ldg(w+11), w22=__ldg(w+12), w23=__ldg(w+13), w24=__ldg(w+14);

    if (v >= n) return;

    const int4 c = ((const int4*)coords)[v];         // (b, z, y, x)
    const int kz = tap >> 4, ky = (tap >> 2) & 3, kx = tap & 3;
    const int oz = c.y - kz, oy = c.z - ky, ox = c.w - kx;
    if ((unsigned)oz >= (unsigned)DMID ||
        (unsigned)oy >= (unsigned)DMID ||
        (unsigned)ox >= (unsigned)DMID) return;

    const float v0 = __ldg(voxels + 3*v + 0);
    const float v1 = __ldg(voxels + 3*v + 1);
    const float v2 = __ldg(voxels + 3*v + 2);

    float s0 = v0*w00 + v1*w10 + v2*w20;
    float s1 = v0*w01 + v1*w11 + v2*w21;
    float s2 = v0*w02 + v1*w12 + v2*w22;
    float s3 = v0*w03 + v1*w13 + v2*w23;
    float s4 = v0*w04 + v1*w14 + v2*w24;

    size_t idx4 = ((((size_t)c.x*DMID + oz)*DMID + oy)*DMID + ox) * 2;
    float4* p = g_mid4 + idx4;
    asm volatile("red.global.add.v4.f32 [%0], {%1, %2, %3, %4};"
                 :: "l"(p), "f"(s0), "f"(s1), "f"(s2), "f"(s3) : "memory");
    asm volatile("red.global.add.f32 [%0], %1;"
                 :: "l"((float*)(p + 1)), "f"(s4) : "memory");
}

// ================= Stage B: 3^3 conv, 5ch -> 3ch, +bias, relu =================
#define BBX 4
#define BTY 8
#define BTZ 4
#define BRX 8
#define BTX (BBX*BRX)        // 32
#define BSZ (BTZ+2)          // 6
#define BSY (BTY+2)          // 10
#define BSXV 34              // voxels per smem row (32+2)
#define BSROW 172            // floats per smem row (170 used, padded)
#define BW_ROW 48            // padded weight row stride (45 used)

__global__ __launch_bounds__(128, 5)
void convB_kernel(const float* __restrict__ W3, const float* __restrict__ b3,
                  float* __restrict__ out) {
    __shared__ float smem[BSZ*BSY*BSROW + 9*BW_ROW];   // 10320 + 432 floats
    float* wsm = smem + BSZ*BSY*BSROW;

    const int tx = threadIdx.x, ty = threadIdx.y, tz = threadIdx.z;
    const int tid = tx + BBX*(ty + BTY*tz);

    const int x0 = blockIdx.x * BTX;
    const int y0 = blockIdx.y * BTY;
    const int NBZ = (DOUT + BTZ - 1) / BTZ;   // 31
    const int b  = blockIdx.z / NBZ;
    const int z0 = (blockIdx.z % NBZ) * BTZ;

    // ---- tile load: 6 x 10 x 34 voxels from 8-stride g_mid4, repacked to 5-stride ----
    {
        const float4* src = g_mid4 + (size_t)b*DMID*DMID*DMID*2;
        #pragma unroll 1
        for (int i = tid; i < BSZ*BSY*BSXV; i += 128) {
            int zz = i / (BSY*BSXV);
            int r  = i - zz*(BSY*BSXV);
            int yy = r / BSXV;
            int xx = r - yy*BSXV;
            int gz = min(z0 + zz, DMID-1);
            int gy = min(y0 + yy, DMID-1);
            int gx = min(x0 + xx, DMID-1);
            size_t s = (((size_t)gz*DMID + gy)*DMID + gx) * 2;
            float4 a = __ldg(src + s);
            float  c4 = __ldg((const float*)(src + s + 1));
            float* d = &smem[(zz*BSY + yy)*BSROW + xx*5];
            d[0] = a.x; d[1] = a.y; d[2] = a.z; d[3] = a.w; d[4] = c4;
        }
        for (int i = tid; i < 9*45; i += 128) {
            int row = i / 45, t = i - row*45;
            wsm[row*BW_ROW + t] = W3[row*45 + t];
        }
    }
    __syncthreads();

    float acc[BRX][COUT];
    #pragma unroll
    for (int j = 0; j < BRX; j++)
        #pragma unroll
        for (int c = 0; c < COUT; c++) acc[j][c] = 0.f;

    #pragma unroll 1
    for (int kz = 0; kz < 3; kz++) {
        #pragma unroll 1
        for (int ky = 0; ky < 3; ky++) {
            const float4* rp = (const float4*)&smem[((tz + kz)*BSY + (ty + ky))*BSROW + tx*(BRX*CMID)];
            union { float4 q[13]; float f[52]; } r;
            #pragma unroll
            for (int i = 0; i < 13; i++) r.q[i] = rp[i];

            const float* wp = wsm + (kz*3 + ky)*BW_ROW;   // 15 taps x 3 cout
            #pragma unroll
            for (int t = 0; t < 15; t++) {
                float w0 = wp[t*3+0], w1 = wp[t*3+1], w2 = wp[t*3+2];
                #pragma unroll
                for (int j = 0; j < BRX; j++) {
                    float xv = r.f[j*CMID + t];
                    acc[j][0] = fmaf(xv, w0, acc[j][0]);
                    acc[j][1] = fmaf(xv, w1, acc[j][1]);
                    acc[j][2] = fmaf(xv, w2, acc[j][2]);
                }
            }
        }
    }

    // ---- epilogue: scalar stores (out rows are 369 floats -> only 4B aligned) ----
    const float bb0 = b3[0], bb1 = b3[1], bb2 = b3[2];
    const int oz = z0 + tz, oy = y0 + ty;
    if (oz < DOUT && oy < DOUT) {
        float* dst = out + (((size_t)b*DOUT + oz)*DOUT + oy)*(size_t)(DOUT*COUT);
        const int oxb = x0 + tx*BRX;
        #pragma unroll
        for (int j = 0; j < BRX; j++) {
            int ox = oxb + j;
            if (ox < DOUT) {
                dst[ox*COUT + 0] = fmaxf(acc[j][0] + bb0, 0.f);
                dst[ox*COUT + 1] = fmaxf(acc[j][1] + bb1, 0.f);
                dst[ox*COUT + 2] = fmaxf(acc[j][2] + bb2, 0.f);
            }
        }
    }
}

// ---------------- launch ----------------
extern "C" void kernel_launch(void* const* d_in, const int* in_sizes, int n_in,
                              void* d_out, int out_size) {
    const int*   coords = (const int*)  d_in[0];
    const float* voxels = (const float*)d_in[1];
    const float* W1     = (const float*)d_in[2];
    const float* W2     = (const float*)d_in[3];
    const float* W3     = (const float*)d_in[4];
    const float* b3     = (const float*)d_in[5];
    float*       out    = (float*)d_out;

    const int n = in_sizes[0] / 4;

    // compose W12 (tiny)
    compose_w12_kernel<<< (4*4*4*3*5 + 255)/256, 256 >>>(W1, W2);

    // zero the mid grid (125 MB)
    void* midp = nullptr;
    cudaGetSymbolAddress(&midp, g_mid4);
    cudaMemsetAsync(midp, 0, (size_t)BATCH*DMID*DMID*DMID*2*sizeof(float4));

    // Stage A: sparse scatter conv (voxel x 64 taps)
    {
        dim3 block(256);
        dim3 grid((n + 255)/256, 64);
        scatterA_kernel<<<grid, block>>>(coords, voxels, n);
    }

    // Stage B: 3^3 conv 5->3 + bias + relu
    {
        dim3 block(BBX, BTY, BTZ);
        dim3 grid((DOUT + BTX - 1)/BTX,            // 4
                  (DOUT + BTY - 1)/BTY,            // 16
                  BATCH * ((DOUT + BTZ - 1)/BTZ)); // 62
        convB_kernel<<<grid, block>>>(W3, b3, out);
    }
}

// round 12
// speedup vs baseline: 1.7787x; 1.1078x over previous
#include <cuda_runtime.h>
#include <cuda_bf16.h>
#include <math.h>

// Problem constants
#define BATCH 2
#define DGRID 128
#define DMID  125          // after 4^3 composed conv
#define DOUT  123          // after 3^3 conv
#define CIN   3
#define CMID  5
#define COUT  3

#define NVOX_MID ((size_t)BATCH*DMID*DMID*DMID)   // 3,906,250

// ---------------- device scratch ----------------
// mid grid split into two planes: ch0-3 (float4) + ch4 (float)
__device__ float4 g_midA[NVOX_MID + 8];   // 62.5 MB
__device__ float  g_midB[NVOX_MID + 8];   // 15.6 MB

// ---------------- Stage A: sparse scatter with on-the-fly composed weights ----
// grid: (ceil(n/128), 16); blockIdx.y = kz*4+ky; thread = one voxel
// Each block first composes its 4 kx-taps' weights (60 floats) from W1,W2.
__global__ __launch_bounds__(128)
void scatterA_kernel(const int* __restrict__ coords,
                     const float* __restrict__ voxels,
                     const float* __restrict__ W1,
                     const float* __restrict__ W2, int n) {
    __shared__ float wsm[60];     // [kx][ci][c5]

    const int kz = blockIdx.y >> 2;
    const int ky = blockIdx.y & 3;

    // ---- compose W12[kz][ky][kx][ci][c5] for kx=0..3 ----
    if (threadIdx.x < 60) {
        int kx = threadIdx.x / 15;
        int r  = threadIdx.x % 15;
        int ci = r / 5, c5 = r % 5;
        float s = 0.f;
        #pragma unroll
        for (int az = 0; az < 2; az++) {
            int bz = kz - az; if (bz < 0 || bz > 2) continue;
            #pragma unroll
            for (int ay = 0; ay < 2; ay++) {
                int by = ky - ay; if (by < 0 || by > 2) continue;
                #pragma unroll
                for (int ax = 0; ax < 2; ax++) {
                    int bx = kx - ax; if (bx < 0 || bx > 2) continue;
                    const float* w1 = W1 + (((az*2 + ay)*2 + ax)*3 + ci)*9;
                    const float* w2 = W2 + ((bz*3 + by)*3 + bx)*9*5;
                    #pragma unroll
                    for (int m = 0; m < 9; m++)
                        s += w1[m] * w2[m*5 + c5];
                }
            }
        }
        wsm[threadIdx.x] = s;
    }
    __syncthreads();

    const int v = blockIdx.x * blockDim.x + threadIdx.x;
    if (v >= n) return;

    const int4 c = ((const int4*)coords)[v];         // (b, z, y, x)
    const int oz = c.y - kz;
    const int oy = c.z - ky;
    if ((unsigned)oz >= (unsigned)DMID || (unsigned)oy >= (unsigned)DMID) return;

    const float v0 = __ldg(voxels + 3*v + 0);
    const float v1 = __ldg(voxels + 3*v + 1);
    const float v2 = __ldg(voxels + 3*v + 2);

    const size_t rowbase = (((size_t)c.x*DMID + oz)*DMID + oy)*DMID;

    #pragma unroll
    for (int kx = 0; kx < 4; kx++) {
        int ox = c.w - kx;
        if ((unsigned)ox >= (unsigned)DMID) continue;
        const float* w = wsm + kx*15;
        float s0 = v0*w[0]  + v1*w[5]  + v2*w[10];
        float s1 = v0*w[1]  + v1*w[6]  + v2*w[11];
        float s2 = v0*w[2]  + v1*w[7]  + v2*w[12];
        float s3 = v0*w[3]  + v1*w[8]  + v2*w[13];
        float s4 = v0*w[4]  + v1*w[9]  + v2*w[14];

        float4* pA = g_midA + rowbase + ox;
        float*  pB = g_midB + rowbase + ox;
        asm volatile("red.global.add.v4.f32 [%0], {%1, %2, %3, %4};"
                     :: "l"(pA), "f"(s0), "f"(s1), "f"(s2), "f"(s3) : "memory");
        asm volatile("red.global.add.f32 [%0], %1;"
                     :: "l"(pB), "f"(s4) : "memory");
    }
}

// ================= Stage B: 3^3 conv, 5ch -> 3ch, +bias, relu =================
#define BBX 4
#define BTY 8
#define BTZ 4
#define BRX 8
#define BTX (BBX*BRX)        // 32
#define BSZ (BTZ+2)          // 6
#define BSY (BTY+2)          // 10
#define BSXV 34              // voxels per smem row (32+2)
#define BSROW 172            // floats per smem row (170 used, padded)
#define BW_ROW 48            // padded weight row stride (45 used)

__global__ __launch_bounds__(128, 5)
void convB_kernel(const float* __restrict__ W3, const float* __restrict__ b3,
                  float* __restrict__ out) {
    __shared__ float smem[BSZ*BSY*BSROW + 9*BW_ROW];   // 10320 + 432 floats
    float* wsm = smem + BSZ*BSY*BSROW;

    const int tx = threadIdx.x, ty = threadIdx.y, tz = threadIdx.z;
    const int tid = tx + BBX*(ty + BTY*tz);

    const int x0 = blockIdx.x * BTX;
    const int y0 = blockIdx.y * BTY;
    const int NBZ = (DOUT + BTZ - 1) / BTZ;   // 31
    const int b  = blockIdx.z / NBZ;
    const int z0 = (blockIdx.z % NBZ) * BTZ;

    // ---- tile load: 6 x 10 x 34 voxels from the two planes, repack to 5-stride ----
    {
        const float4* srcA = g_midA + (size_t)b*DMID*DMID*DMID;
        const float*  srcB = g_midB + (size_t)b*DMID*DMID*DMID;
        #pragma unroll 1
        for (int i = tid; i < BSZ*BSY*BSXV; i += 128) {
            int zz = i / (BSY*BSXV);
            int r  = i - zz*(BSY*BSXV);
            int yy = r / BSXV;
            int xx = r - yy*BSXV;
            int gz = min(z0 + zz, DMID-1);
            int gy = min(y0 + yy, DMID-1);
            int gx = min(x0 + xx, DMID-1);
            size_t s = ((size_t)gz*DMID + gy)*DMID + gx;
            float4 a  = __ldg(srcA + s);
            float  c4 = __ldg(srcB + s);
            float* d = &smem[(zz*BSY + yy)*BSROW + xx*5];
            d[0] = a.x; d[1] = a.y; d[2] = a.z; d[3] = a.w; d[4] = c4;
        }
        for (int i = tid; i < 9*45; i += 128) {
            int row = i / 45, t = i - row*45;
            wsm[row*BW_ROW + t] = W3[row*45 + t];
        }
    }
    __syncthreads();

    float acc[BRX][COUT];
    #pragma unroll
    for (int j = 0; j < BRX; j++)
        #pragma unroll
        for (int c = 0; c < COUT; c++) acc[j][c] = 0.f;

    #pragma unroll 1
    for (int kz = 0; kz < 3; kz++) {
        #pragma unroll 1
        for (int ky = 0; ky < 3; ky++) {
            const float4* rp = (const float4*)&smem[((tz + kz)*BSY + (ty + ky))*BSROW + tx*(BRX*CMID)];
            union { float4 q[13]; float f[52]; } r;
            #pragma unroll
            for (int i = 0; i < 13; i++) r.q[i] = rp[i];

            const float* wp = wsm + (kz*3 + ky)*BW_ROW;   // 15 taps x 3 cout
            #pragma unroll
            for (int t = 0; t < 15; t++) {
                float w0 = wp[t*3+0], w1 = wp[t*3+1], w2 = wp[t*3+2];
                #pragma unroll
                for (int j = 0; j < BRX; j++) {
                    float xv = r.f[j*CMID + t];
                    acc[j][0] = fmaf(xv, w0, acc[j][0]);
                    acc[j][1] = fmaf(xv, w1, acc[j][1]);
                    acc[j][2] = fmaf(xv, w2, acc[j][2]);
                }
            }
        }
    }

    // ---- epilogue: scalar stores (out rows are 369 floats -> only 4B aligned) ----
    const float bb0 = b3[0], bb1 = b3[1], bb2 = b3[2];
    const int oz = z0 + tz, oy = y0 + ty;
    if (oz < DOUT && oy < DOUT) {
        float* dst = out + (((size_t)b*DOUT + oz)*DOUT + oy)*(size_t)(DOUT*COUT);
        const int oxb = x0 + tx*BRX;
        #pragma unroll
        for (int j = 0; j < BRX; j++) {
            int ox = oxb + j;
            if (ox < DOUT) {
                dst[ox*COUT + 0] = fmaxf(acc[j][0] + bb0, 0.f);
                dst[ox*COUT + 1] = fmaxf(acc[j][1] + bb1, 0.f);
                dst[ox*COUT + 2] = fmaxf(acc[j][2] + bb2, 0.f);
            }
        }
    }
}

// ---------------- launch ----------------
extern "C" void kernel_launch(void* const* d_in, const int* in_sizes, int n_in,
                              void* d_out, int out_size) {
    const int*   coords = (const int*)  d_in[0];
    const float* voxels = (const float*)d_in[1];
    const float* W1     = (const float*)d_in[2];
    const float* W2     = (const float*)d_in[3];
    const float* W3     = (const float*)d_in[4];
    const float* b3     = (const float*)d_in[5];
    float*       out    = (float*)d_out;

    const int n = in_sizes[0] / 4;

    // zero the two mid planes (62.5 MB + 15.6 MB)
    void* pA = nullptr; void* pB = nullptr;
    cudaGetSymbolAddress(&pA, g_midA);
    cudaGetSymbolAddress(&pB, g_midB);
    cudaMemsetAsync(pA, 0, NVOX_MID*sizeof(float4));
    cudaMemsetAsync(pB, 0, NVOX_MID*sizeof(float));

    // Stage A: sparse scatter conv (thread = voxel x (kz,ky))
    {
        dim3 block(128);
        dim3 grid((n + 127)/128, 16);
        scatterA_kernel<<<grid, block>>>(coords, voxels, W1, W2, n);
    }

    // Stage B: 3^3 conv 5->3 + bias + relu
    {
        dim3 block(BBX, BTY, BTZ);
        dim3 grid((DOUT + BTX - 1)/BTX,            // 4
                  (DOUT + BTY - 1)/BTY,            // 16
                  BATCH * ((DOUT + BTZ - 1)/BTZ)); // 62
        convB_kernel<<<grid, block>>>(W3, b3, out);
    }
}

// round 14
// speedup vs baseline: 2.6078x; 1.4661x over previous
#include <cuda_runtime.h>
#include <cuda_bf16.h>
#include <math.h>

// Problem constants
#define BATCH 2
#define DGRID 128
#define DMID  125          // after 4^3 composed conv
#define DOUT  123          // after 3^3 conv
#define CIN   3
#define CMID  5
#define COUT  3

#define NVOX_MID ((size_t)BATCH*DMID*DMID*DMID)   // 3,906,250

// ---------------- device scratch ----------------
// mid grid split into two planes: ch0-3 (float4) + ch4 (float)
__device__ float4 g_midA[NVOX_MID + 8];   // 62.5 MB
__device__ float  g_midB[NVOX_MID + 8];   // 15.6 MB

// ---------------- Stage A: sparse scatter with on-the-fly composed weights ----
// grid: (ceil(n/128), 16); blockIdx.y = kz*4+ky; thread = one voxel
__global__ __launch_bounds__(128)
void scatterA_kernel(const int* __restrict__ coords,
                     const float* __restrict__ voxels,
                     const float* __restrict__ W1,
                     const float* __restrict__ W2, int n) {
    __shared__ float wsm[60];     // [kx][ci][c5]

    const int kz = blockIdx.y >> 2;
    const int ky = blockIdx.y & 3;

    // ---- compose W12[kz][ky][kx][ci][c5] for kx=0..3 ----
    if (threadIdx.x < 60) {
        int kx = threadIdx.x / 15;
        int r  = threadIdx.x % 15;
        int ci = r / 5, c5 = r % 5;
        float s = 0.f;
        #pragma unroll
        for (int az = 0; az < 2; az++) {
            int bz = kz - az; if (bz < 0 || bz > 2) continue;
            #pragma unroll
            for (int ay = 0; ay < 2; ay++) {
                int by = ky - ay; if (by < 0 || by > 2) continue;
                #pragma unroll
                for (int ax = 0; ax < 2; ax++) {
                    int bx = kx - ax; if (bx < 0 || bx > 2) continue;
                    const float* w1 = W1 + (((az*2 + ay)*2 + ax)*3 + ci)*9;
                    const float* w2 = W2 + ((bz*3 + by)*3 + bx)*9*5;
                    #pragma unroll
                    for (int m = 0; m < 9; m++)
                        s += w1[m] * w2[m*5 + c5];
                }
            }
        }
        wsm[threadIdx.x] = s;
    }
    __syncthreads();

    const int v = blockIdx.x * blockDim.x + threadIdx.x;
    if (v >= n) return;

    const int4 c = ((const int4*)coords)[v];         // (b, z, y, x)
    const int oz = c.y - kz;
    const int oy = c.z - ky;
    if ((unsigned)oz >= (unsigned)DMID || (unsigned)oy >= (unsigned)DMID) return;

    const float v0 = __ldg(voxels + 3*v + 0);
    const float v1 = __ldg(voxels + 3*v + 1);
    const float v2 = __ldg(voxels + 3*v + 2);

    const size_t rowbase = (((size_t)c.x*DMID + oz)*DMID + oy)*DMID;

    #pragma unroll
    for (int kx = 0; kx < 4; kx++) {
        int ox = c.w - kx;
        if ((unsigned)ox >= (unsigned)DMID) continue;
        const float* w = wsm + kx*15;
        float s0 = v0*w[0]  + v1*w[5]  + v2*w[10];
        float s1 = v0*w[1]  + v1*w[6]  + v2*w[11];
        float s2 = v0*w[2]  + v1*w[7]  + v2*w[12];
        float s3 = v0*w[3]  + v1*w[8]  + v2*w[13];
        float s4 = v0*w[4]  + v1*w[9]  + v2*w[14];

        float4* pA = g_midA + rowbase + ox;
        float*  pB = g_midB + rowbase + ox;
        asm volatile("red.global.add.v4.f32 [%0], {%1, %2, %3, %4};"
                     :: "l"(pA), "f"(s0), "f"(s1), "f"(s2), "f"(s3) : "memory");
        asm volatile("red.global.add.f32 [%0], %1;"
                     :: "l"(pB), "f"(s4) : "memory");
    }
}

// ================= Stage B: 3^3 conv, 5ch -> 3ch, +bias, relu =================
// block (8,4,4): threadIdx.x = ty (fast lane dim), .y = x-chunk, .z = tz
#define BTY 8
#define BBX 4
#define BTZ 4
#define BRX 8
#define BTX (BBX*BRX)        // 32
#define BSZ (BTZ+2)          // 6
#define BSY (BTY+2)          // 10
#define BSXV 34              // voxels per smem row (32+2)
#define SRA 140              // planeA row stride, floats (136 used; 560B == 48 mod 128)
#define SRB 36               // planeB row stride, floats (34 used; 144B == 16 mod 128)
#define BW_ROW 48            // padded weight row stride (45 used)
#define STG_ROW 98           // staging row stride, floats (96 used; 98%32=2 -> no ty-bank clash)

__global__ __launch_bounds__(128, 5)
void convB_kernel(const float* __restrict__ W3, const float* __restrict__ b3,
                  float* __restrict__ out) {
    __shared__ float smA[BSZ*BSY*SRA];     // 8400 floats
    __shared__ float smB[BSZ*BSY*SRB];     // 2160 floats
    __shared__ float wsm[9*BW_ROW];        // 432 floats

    const int ty  = threadIdx.x;           // 0..7  (fast lane dim, y within tile)
    const int txc = threadIdx.y;           // 0..3  (x chunk)
    const int tz  = threadIdx.z;           // 0..3  (z within tile)
    const int tid = ty + BTY*(txc + BBX*tz);

    const int x0 = blockIdx.x * BTX;
    const int y0 = blockIdx.y * BTY;
    const int NBZ = (DOUT + BTZ - 1) / BTZ;   // 31
    const int b  = blockIdx.z / NBZ;
    const int z0 = (blockIdx.z % NBZ) * BTZ;

    // ---- tile load: 6 x 10 x 34 voxels, direct STS (no repack) ----
    {
        const float4* srcA = g_midA + (size_t)b*DMID*DMID*DMID;
        const float*  srcB = g_midB + (size_t)b*DMID*DMID*DMID;
        #pragma unroll 1
        for (int i = tid; i < BSZ*BSY*BSXV; i += 128) {
            int zz = i / (BSY*BSXV);
            int r  = i - zz*(BSY*BSXV);
            int yy = r / BSXV;
            int xx = r - yy*BSXV;
            int gz = min(z0 + zz, DMID-1);
            int gy = min(y0 + yy, DMID-1);
            int gx = min(x0 + xx, DMID-1);
            size_t s = ((size_t)gz*DMID + gy)*DMID + gx;
            float4 a = __ldg(srcA + s);
            *(float4*)&smA[(zz*BSY + yy)*SRA + xx*4] = a;
            smB[(zz*BSY + yy)*SRB + xx] = __ldg(srcB + s);
        }
        for (int i = tid; i < 9*45; i += 128) {
            int row = i / 45, t = i - row*45;
            wsm[row*BW_ROW + t] = W3[row*45 + t];
        }
    }
    __syncthreads();

    float acc[BRX][COUT];
    #pragma unroll
    for (int j = 0; j < BRX; j++)
        #pragma unroll
        for (int c = 0; c < COUT; c++) acc[j][c] = 0.f;

    #pragma unroll 1
    for (int kz = 0; kz < 3; kz++) {
        #pragma unroll 1
        for (int ky = 0; ky < 3; ky++) {
            // planeA: 10 float4 sliding window (ch0-3 for voxels txc*8 .. txc*8+9)
            const float4* rpA = (const float4*)&smA[((tz + kz)*BSY + (ty + ky))*SRA + txc*(BRX*4)];
            union { float4 q[10]; float f[40]; } ra;
            #pragma unroll
            for (int i = 0; i < 10; i++) ra.q[i] = rpA[i];
            // planeB: 12 floats (10 used) as 3 float4
            const float4* rpB = (const float4*)&smB[((tz + kz)*BSY + (ty + ky))*SRB + txc*BRX];
            union { float4 q[3]; float f[12]; } rb;
            #pragma unroll
            for (int i = 0; i < 3; i++) rb.q[i] = rpB[i];

            const float* wp = wsm + (kz*3 + ky)*BW_ROW;   // 15 taps x 3 cout

            #pragma unroll
            for (int kx = 0; kx < 3; kx++) {
                #pragma unroll
                for (int ci = 0; ci < 4; ci++) {
                    const int t = kx*5 + ci;
                    float w0 = wp[t*3+0], w1 = wp[t*3+1], w2 = wp[t*3+2];
                    #pragma unroll
                    for (int j = 0; j < BRX; j++) {
                        float xv = ra.f[(j + kx)*4 + ci];
                        acc[j][0] = fmaf(xv, w0, acc[j][0]);
                        acc[j][1] = fmaf(xv, w1, acc[j][1]);
                        acc[j][2] = fmaf(xv, w2, acc[j][2]);
                    }
                }
                {   // ci = 4 from planeB
                    const int t = kx*5 + 4;
                    float w0 = wp[t*3+0], w1 = wp[t*3+1], w2 = wp[t*3+2];
                    #pragma unroll
                    for (int j = 0; j < BRX; j++) {
                        float xv = rb.f[j + kx];
                        acc[j][0] = fmaf(xv, w0, acc[j][0]);
                        acc[j][1] = fmaf(xv, w1, acc[j][1]);
                        acc[j][2] = fmaf(xv, w2, acc[j][2]);
                    }
                }
            }
        }
    }

    // ---- epilogue: bias + relu, stage through smem (output-linear), coalesced store ----
    const float bb0 = b3[0], bb1 = b3[1], bb2 = b3[2];
    __syncthreads();                 // mainloop reads done; reuse smA as staging
    {
        // staging layout: [tz][ty] rows of STG_ROW floats, 96 used = (txc,j,c)
        float* s = smA + (tz*BTY + ty)*STG_ROW + txc*(BRX*3);
        #pragma unroll
        for (int j = 0; j < BRX; j++) {
            s[j*3+0] = fmaxf(acc[j][0] + bb0, 0.f);
            s[j*3+1] = fmaxf(acc[j][1] + bb1, 0.f);
            s[j*3+2] = fmaxf(acc[j][2] + bb2, 0.f);
        }
    }
    __syncthreads();
    {
        const float* stg = smA;
        const int oxcap = (min(DOUT - x0, BTX)) * 3;   // valid floats per row
        #pragma unroll 1
        for (int i = tid; i < BTZ*BTY*BTX*3; i += 128) {   // 3072
            int row = i / (BTX*3);          // tz2*8 + ty2
            int xc  = i - row*(BTX*3);
            int tz2 = row >> 3, ty2 = row & 7;
            int oz = z0 + tz2, oy = y0 + ty2;
            if (oz < DOUT && oy < DOUT && xc < oxcap) {
                out[(((size_t)b*DOUT + oz)*DOUT + oy)*(size_t)(DOUT*3)
                    + (size_t)x0*3 + xc] = stg[row*STG_ROW + xc];
            }
        }
    }
}

// ---------------- launch ----------------
extern "C" void kernel_launch(void* const* d_in, const int* in_sizes, int n_in,
                              void* d_out, int out_size) {
    const int*   coords = (const int*)  d_in[0];
    const float* voxels = (const float*)d_in[1];
    const float* W1     = (const float*)d_in[2];
    const float* W2     = (const float*)d_in[3];
    const float* W3     = (const float*)d_in[4];
    const float* b3     = (const float*)d_in[5];
    float*       out    = (float*)d_out;

    const int n = in_sizes[0] / 4;

    // zero the two mid planes (62.5 MB + 15.6 MB)
    void* pA = nullptr; void* pB = nullptr;
    cudaGetSymbolAddress(&pA, g_midA);
    cudaGetSymbolAddress(&pB, g_midB);
    cudaMemsetAsync(pA, 0, NVOX_MID*sizeof(float4));
    cudaMemsetAsync(pB, 0, NVOX_MID*sizeof(float));

    // Stage A: sparse scatter conv (thread = voxel x (kz,ky))
    {
        dim3 block(128);
        dim3 grid((n + 127)/128, 16);
        scatterA_kernel<<<grid, block>>>(coords, voxels, W1, W2, n);
    }

    // Stage B: 3^3 conv 5->3 + bias + relu
    {
        dim3 block(BTY, BBX, BTZ);                 // (8,4,4) = 128
        dim3 grid((DOUT + BTX - 1)/BTX,            // 4
                  (DOUT + BTY - 1)/BTY,            // 16
                  BATCH * ((DOUT + BTZ - 1)/BTZ)); // 62
        convB_kernel<<<grid, block>>>(W3, b3, out);
    }
}

// round 15
// speedup vs baseline: 2.6967x; 1.0341x over previous
#include <cuda_runtime.h>
#include <cuda_bf16.h>
#include <math.h>

// Problem constants
#define BATCH 2
#define DGRID 128
#define DMID  125          // after 4^3 composed conv
#define DOUT  123          // after 3^3 conv
#define CIN   3
#define CMID  5
#define COUT  3

#define NVOX_MID ((size_t)BATCH*DMID*DMID*DMID)   // 3,906,250

// ---------------- device scratch ----------------
// mid grid split into two planes: ch0-3 (float4) + ch4 (float)
__device__ float4 g_midA[NVOX_MID + 8];   // 62.5 MB
__device__ float  g_midB[NVOX_MID + 8];   // 15.6 MB

// ---------------- Stage A: sparse scatter with on-the-fly composed weights ----
// grid: (ceil(n/128), 4); blockIdx.y = kz; ky,kx in-register loops
__global__ __launch_bounds__(128)
void scatterA_kernel(const int* __restrict__ coords,
                     const float* __restrict__ voxels,
                     const float* __restrict__ W1,
                     const float* __restrict__ W2, int n) {
    __shared__ float wsm[240];     // [ky][kx][ci][c5]

    const int kz = blockIdx.y;

    // ---- compose W12[kz][ky][kx][ci][c5] for ky,kx = 0..3 ----
    for (int idx = threadIdx.x; idx < 240; idx += 128) {
        int ky = idx / 60;
        int kx = (idx / 15) & 3;
        int r  = idx % 15;
        int ci = r / 5, c5 = r % 5;
        float s = 0.f;
        #pragma unroll
        for (int az = 0; az < 2; az++) {
            int bz = kz - az; if (bz < 0 || bz > 2) continue;
            #pragma unroll
            for (int ay = 0; ay < 2; ay++) {
                int by = ky - ay; if (by < 0 || by > 2) continue;
                #pragma unroll
                for (int ax = 0; ax < 2; ax++) {
                    int bx = kx - ax; if (bx < 0 || bx > 2) continue;
                    const float* w1 = W1 + (((az*2 + ay)*2 + ax)*3 + ci)*9;
                    const float* w2 = W2 + ((bz*3 + by)*3 + bx)*9*5;
                    #pragma unroll
                    for (int m = 0; m < 9; m++)
                        s += w1[m] * w2[m*5 + c5];
                }
            }
        }
        wsm[idx] = s;
    }
    __syncthreads();

    const int v = blockIdx.x * blockDim.x + threadIdx.x;
    if (v >= n) return;

    const int4 c = ((const int4*)coords)[v];         // (b, z, y, x)
    const int oz = c.y - kz;
    if ((unsigned)oz >= (unsigned)DMID) return;

    const float v0 = __ldg(voxels + 3*v + 0);
    const float v1 = __ldg(voxels + 3*v + 1);
    const float v2 = __ldg(voxels + 3*v + 2);

    const size_t zbase = (((size_t)c.x*DMID + oz)*DMID);

    #pragma unroll
    for (int ky = 0; ky < 4; ky++) {
        int oy = c.z - ky;
        if ((unsigned)oy >= (unsigned)DMID) continue;
        const size_t rowbase = (zbase + oy)*DMID;
        #pragma unroll
        for (int kx = 0; kx < 4; kx++) {
            int ox = c.w - kx;
            if ((unsigned)ox >= (unsigned)DMID) continue;
            const float* w = wsm + (ky*4 + kx)*15;
            float s0 = v0*w[0]  + v1*w[5]  + v2*w[10];
            float s1 = v0*w[1]  + v1*w[6]  + v2*w[11];
            float s2 = v0*w[2]  + v1*w[7]  + v2*w[12];
            float s3 = v0*w[3]  + v1*w[8]  + v2*w[13];
            float s4 = v0*w[4]  + v1*w[9]  + v2*w[14];

            float4* pA = g_midA + rowbase + ox;
            float*  pB = g_midB + rowbase + ox;
            asm volatile("red.global.add.v4.f32 [%0], {%1, %2, %3, %4};"
                         :: "l"(pA), "f"(s0), "f"(s1), "f"(s2), "f"(s3) : "memory");
            asm volatile("red.global.add.f32 [%0], %1;"
                         :: "l"(pB), "f"(s4) : "memory");
        }
    }
}

// ================= Stage B: 3^3 conv, 5ch -> 3ch, +bias, relu =================
// block (8,4,4): threadIdx.x = ty (fast lane dim), .y = x-chunk, .z = tz
#define BTY 8
#define BBX 4
#define BTZ 4
#define BRX 8
#define BTX (BBX*BRX)        // 32
#define BSZ (BTZ+2)          // 6
#define BSY (BTY+2)          // 10
#define BSXV 34              // voxels per smem row (32+2)
#define SRA 140              // planeA row stride, floats (136 used; 560B == 48 mod 128)
#define SRB 36               // planeB row stride, floats (34 used; 144B == 16 mod 128)
#define BW_ROW 48            // padded weight row stride (45 used)
#define STG_ROW 98           // staging row stride, floats (96 used; 98%32=2)

__global__ __launch_bounds__(128, 5)
void convB_kernel(const float* __restrict__ W3, const float* __restrict__ b3,
                  float* __restrict__ out) {
    __shared__ float smA[BSZ*BSY*SRA];     // 8400 floats
    __shared__ float smB[BSZ*BSY*SRB];     // 2160 floats
    __shared__ float wsm[9*BW_ROW];        // 432 floats

    const int ty  = threadIdx.x;           // 0..7  (fast lane dim, y within tile)
    const int txc = threadIdx.y;           // 0..3  (x chunk)
    const int tz  = threadIdx.z;           // 0..3  (z within tile)
    const int tid = ty + BTY*(txc + BBX*tz);

    const int x0 = blockIdx.x * BTX;
    const int y0 = blockIdx.y * BTY;
    const int NBZ = (DOUT + BTZ - 1) / BTZ;   // 31
    const int b  = blockIdx.z / NBZ;
    const int z0 = (blockIdx.z % NBZ) * BTZ;

    // ---- tile load: (y,x) outer / z inner, minimal index math ----
    {
        const float4* srcA = g_midA + (size_t)b*DMID*DMID*DMID;
        const float*  srcB = g_midB + (size_t)b*DMID*DMID*DMID;
        #pragma unroll 1
        for (int i = tid; i < BSY*BSXV; i += 128) {    // 340 -> ~3 iters
            int yy = i / BSXV;
            int xx = i - yy*BSXV;
            int gy = min(y0 + yy, DMID-1);
            int gx = min(x0 + xx, DMID-1);
            size_t s0 = (size_t)gy*DMID + gx;
            int dA = yy*SRA + xx*4;
            int dB = yy*SRB + xx;
            #pragma unroll
            for (int zz = 0; zz < BSZ; zz++) {
                int gz = min(z0 + zz, DMID-1);
                size_t s = (size_t)gz*(DMID*DMID) + s0;
                *(float4*)&smA[zz*(BSY*SRA) + dA] = __ldg(srcA + s);
                smB[zz*(BSY*SRB) + dB] = __ldg(srcB + s);
            }
        }
        for (int i = tid; i < 9*45; i += 128) {
            int row = i / 45, t = i - row*45;
            wsm[row*BW_ROW + t] = W3[row*45 + t];
        }
    }
    __syncthreads();

    float acc[BRX][COUT];
    #pragma unroll
    for (int j = 0; j < BRX; j++)
        #pragma unroll
        for (int c = 0; c < COUT; c++) acc[j][c] = 0.f;

    #pragma unroll 1
    for (int kz = 0; kz < 3; kz++) {
        #pragma unroll 1
        for (int ky = 0; ky < 3; ky++) {
            // planeA: 10 float4 sliding window (ch0-3 for voxels txc*8 .. txc*8+9)
            const float4* rpA = (const float4*)&smA[((tz + kz)*BSY + (ty + ky))*SRA + txc*(BRX*4)];
            union { float4 q[10]; float f[40]; } ra;
            #pragma unroll
            for (int i = 0; i < 10; i++) ra.q[i] = rpA[i];
            // planeB: 12 floats (10 used) as 3 float4
            const float4* rpB = (const float4*)&smB[((tz + kz)*BSY + (ty + ky))*SRB + txc*BRX];
            union { float4 q[3]; float f[12]; } rb;
            #pragma unroll
            for (int i = 0; i < 3; i++) rb.q[i] = rpB[i];

            const float* wp = wsm + (kz*3 + ky)*BW_ROW;   // 15 taps x 3 cout

            #pragma unroll
            for (int kx = 0; kx < 3; kx++) {
                #pragma unroll
                for (int ci = 0; ci < 4; ci++) {
                    const int t = kx*5 + ci;
                    float w0 = wp[t*3+0], w1 = wp[t*3+1], w2 = wp[t*3+2];
                    #pragma unroll
                    for (int j = 0; j < BRX; j++) {
                        float xv = ra.f[(j + kx)*4 + ci];
                        acc[j][0] = fmaf(xv, w0, acc[j][0]);
                        acc[j][1] = fmaf(xv, w1, acc[j][1]);
                        acc[j][2] = fmaf(xv, w2, acc[j][2]);
                    }
                }
                {   // ci = 4 from planeB
                    const int t = kx*5 + 4;
                    float w0 = wp[t*3+0], w1 = wp[t*3+1], w2 = wp[t*3+2];
                    #pragma unroll
                    for (int j = 0; j < BRX; j++) {
                        float xv = rb.f[j + kx];
                        acc[j][0] = fmaf(xv, w0, acc[j][0]);
                        acc[j][1] = fmaf(xv, w1, acc[j][1]);
                        acc[j][2] = fmaf(xv, w2, acc[j][2]);
                    }
                }
            }
        }
    }

    // ---- epilogue: bias + relu, stage through smem (output-linear), coalesced store ----
    const float bb0 = b3[0], bb1 = b3[1], bb2 = b3[2];
    __syncthreads();                 // mainloop reads done; reuse smA as staging
    {
        // staging layout: [tz][ty] rows of STG_ROW floats, 96 used = (txc,j,c)
        float* s = smA + (tz*BTY + ty)*STG_ROW + txc*(BRX*3);
        #pragma unroll
        for (int j = 0; j < BRX; j++) {
            s[j*3+0] = fmaxf(acc[j][0] + bb0, 0.f);
            s[j*3+1] = fmaxf(acc[j][1] + bb1, 0.f);
            s[j*3+2] = fmaxf(acc[j][2] + bb2, 0.f);
        }
    }
    __syncthreads();
    {
        // div-free: thread owns (row = tid>>2, quarter = tid&3) -> 24 floats
        const int row = tid >> 2;            // tz2*8 + ty2
        const int q   = tid & 3;
        const int tz2 = row >> 3, ty2 = row & 7;
        const int oz = z0 + tz2, oy = y0 + ty2;
        if (oz < DOUT && oy < DOUT) {
            const int oxcap = (min(DOUT - x0, BTX)) * 3;   // valid floats in this row
            const int base  = q * 24;
            const float* s = smA + row*STG_ROW + base;
            float* d = out + (((size_t)b*DOUT + oz)*DOUT + oy)*(size_t)(DOUT*3)
                     + (size_t)x0*3 + base;
            const int cap = oxcap - base;                  // 24 interior; 24/24/24/9 edge
            #pragma unroll
            for (int j = 0; j < 24; j++)
                if (j < cap) d[j] = s[j];
        }
    }
}

// ---------------- launch ----------------
extern "C" void kernel_launch(void* const* d_in, const int* in_sizes, int n_in,
                              void* d_out, int out_size) {
    const int*   coords = (const int*)  d_in[0];
    const float* voxels = (const float*)d_in[1];
    const float* W1     = (const float*)d_in[2];
    const float* W2     = (const float*)d_in[3];
    const float* W3     = (const float*)d_in[4];
    const float* b3     = (const float*)d_in[5];
    float*       out    = (float*)d_out;

    const int n = in_sizes[0] / 4;

    // zero the two mid planes (62.5 MB + 15.6 MB)
    void* pA = nullptr; void* pB = nullptr;
    cudaGetSymbolAddress(&pA, g_midA);
    cudaGetSymbolAddress(&pB, g_midB);
    cudaMemsetAsync(pA, 0, NVOX_MID*sizeof(float4));
    cudaMemsetAsync(pB, 0, NVOX_MID*sizeof(float));

    // Stage A: sparse scatter conv (thread = voxel x kz; ky,kx loops)
    {
        dim3 block(128);
        dim3 grid((n + 127)/128, 4);
        scatterA_kernel<<<grid, block>>>(coords, voxels, W1, W2, n);
    }

    // Stage B: 3^3 conv 5->3 + bias + relu
    {
        dim3 block(BTY, BBX, BTZ);                 // (8,4,4) = 128
        dim3 grid((DOUT + BTX - 1)/BTX,            // 4
                  (DOUT + BTY - 1)/BTY,            // 16
                  BATCH * ((DOUT + BTZ - 1)/BTZ)); // 62
        convB_kernel<<<grid, block>>>(W3, b3, out);
    }
}